// round 1
// baseline (speedup 1.0000x reference)
#include <cuda_runtime.h>
#include <cuda_bf16.h>
#include <cstdint>

// Problem constants (fixed by the dataset)
#define N_NODES 100000
#define IN_DIM  256
#define OUT_DIM 128
#define N_EDGES 3200000

// Scratch for h = X @ W  (51.2 MB, static device array — no allocs allowed)
__device__ float g_h[(size_t)N_NODES * OUT_DIM];

// ---------------------------------------------------------------------------
// Kernel 1: out[n, c] = b[c]   (initialize output with bias; d_out is poisoned)
// ---------------------------------------------------------------------------
__global__ void init_bias_kernel(float* __restrict__ out, const float* __restrict__ b) {
    // out has N_NODES*OUT_DIM floats = 3,200,000 float4
    const int total4 = (N_NODES * OUT_DIM) / 4;
    int idx = blockIdx.x * blockDim.x + threadIdx.x;
    const float4* b4 = (const float4*)b;  // 32 float4 per row
    for (int i = idx; i < total4; i += gridDim.x * blockDim.x) {
        ((float4*)out)[i] = b4[i & 31];
    }
}

// ---------------------------------------------------------------------------
// Kernel 2: tiled fp32 GEMM  h[N, 128] = X[N, 256] @ W[256, 128]
// BM=64 rows per block, full 128 cols, BK=32. 256 threads, 8x4 micro-tile.
// ---------------------------------------------------------------------------
#define BM 64
#define BK 32
__global__ __launch_bounds__(256) void gemm_kernel(const float* __restrict__ X,
                                                   const float* __restrict__ W,
                                                   float* __restrict__ H) {
    __shared__ float sA[BM][BK];        // 8 KB
    __shared__ float sB[BK][OUT_DIM];   // 16 KB

    const int tid = threadIdx.x;
    const int tx = tid & 31;            // col group: cols tx*4 .. tx*4+3
    const int ty = tid >> 5;            // row group: rows ty*8 .. ty*8+7
    const int m0 = blockIdx.x * BM;

    float acc[8][4];
#pragma unroll
    for (int i = 0; i < 8; i++)
#pragma unroll
        for (int j = 0; j < 4; j++) acc[i][j] = 0.0f;

    for (int k0 = 0; k0 < IN_DIM; k0 += BK) {
        // Load A tile: 64x32 floats = 512 float4, 2 per thread
#pragma unroll
        for (int i = tid; i < BM * BK / 4; i += 256) {
            int r = i >> 3;             // 8 float4 per row
            int c = (i & 7) << 2;
            float4 v = make_float4(0.f, 0.f, 0.f, 0.f);
            if (m0 + r < N_NODES)
                v = *(const float4*)&X[(size_t)(m0 + r) * IN_DIM + k0 + c];
            *(float4*)&sA[r][c] = v;
        }
        // Load B tile: 32x128 floats = 1024 float4, 4 per thread
#pragma unroll
        for (int i = tid; i < BK * OUT_DIM / 4; i += 256) {
            int r = i >> 5;             // 32 float4 per row
            int c = (i & 31) << 2;
            *(float4*)&sB[r][c] = *(const float4*)&W[(size_t)(k0 + r) * OUT_DIM + c];
        }
        __syncthreads();

#pragma unroll
        for (int kk = 0; kk < BK; kk++) {
            float bReg[4];
#pragma unroll
            for (int j = 0; j < 4; j++) bReg[j] = sB[kk][tx * 4 + j];
#pragma unroll
            for (int i = 0; i < 8; i++) {
                float a = sA[ty * 8 + i][kk];
#pragma unroll
                for (int j = 0; j < 4; j++) acc[i][j] = fmaf(a, bReg[j], acc[i][j]);
            }
        }
        __syncthreads();
    }

#pragma unroll
    for (int i = 0; i < 8; i++) {
        int m = m0 + ty * 8 + i;
        if (m < N_NODES) {
            float4 v = make_float4(acc[i][0], acc[i][1], acc[i][2], acc[i][3]);
            *(float4*)&g_h[(size_t)m * OUT_DIM + tx * 4] = v;
        }
    }
    (void)H;
}

// ---------------------------------------------------------------------------
// Kernel 3: scatter. One warp processes 32 edges; for each edge the warp
// covers all 128 output features (4 per lane, float4). Uses vectorized
// no-return global reduction red.global.add.v4.f32 (sm_90+).
// ---------------------------------------------------------------------------
__global__ __launch_bounds__(256) void scatter_kernel(const int* __restrict__ src,
                                                      const int* __restrict__ dst,
                                                      const float* __restrict__ val,
                                                      float* __restrict__ out) {
    const int warp = (blockIdx.x * blockDim.x + threadIdx.x) >> 5;
    const int lane = threadIdx.x & 31;
    const int base = warp * 32;       // N_EDGES divisible by 32
    if (base >= N_EDGES) return;

    int   s = src[base + lane];
    int   d = dst[base + lane];
    float v = val[base + lane];

#pragma unroll 4
    for (int j = 0; j < 32; j++) {
        int   sj = __shfl_sync(0xffffffffu, s, j);
        int   dj = __shfl_sync(0xffffffffu, d, j);
        float vj = __shfl_sync(0xffffffffu, v, j);

        float4 h4 = *(const float4*)&g_h[(size_t)sj * OUT_DIM + lane * 4];
        float4 m4 = make_float4(h4.x * vj, h4.y * vj, h4.z * vj, h4.w * vj);

        float* p = &out[(size_t)dj * OUT_DIM + lane * 4];
        asm volatile("red.global.add.v4.f32 [%0], {%1, %2, %3, %4};"
                     :: "l"(p), "f"(m4.x), "f"(m4.y), "f"(m4.z), "f"(m4.w)
                     : "memory");
    }
}

// ---------------------------------------------------------------------------
// Launch
// ---------------------------------------------------------------------------
extern "C" void kernel_launch(void* const* d_in, const int* in_sizes, int n_in,
                              void* d_out, int out_size) {
    const float* feature_map = (const float*)d_in[0];
    const int*   edge_src    = (const int*)d_in[1];
    const int*   edge_dst    = (const int*)d_in[2];
    const float* edge_vals   = (const float*)d_in[3];
    const float* weights     = (const float*)d_in[4];
    const float* bias        = (const float*)d_in[5];
    float*       out         = (float*)d_out;

    // 1. out = bias (also clears poison)
    init_bias_kernel<<<1024, 256>>>(out, bias);

    // 2. h = X @ W  (1563 blocks of 64 rows)
    gemm_kernel<<<(N_NODES + BM - 1) / BM, 256>>>(feature_map, weights, nullptr);

    // 3. scatter-add messages: 3.2M edges, 32 edges/warp, 8 warps/block
    scatter_kernel<<<N_EDGES / 256, 256>>>(edge_src, edge_dst, edge_vals, out);

    (void)in_sizes; (void)n_in; (void)out_size;
}

// round 3
// speedup vs baseline: 1.1246x; 1.1246x over previous
#include <cuda_runtime.h>
#include <cuda_bf16.h>
#include <cstdint>

// Problem constants (fixed by the dataset)
#define N_NODES 100000
#define IN_DIM  256
#define OUT_DIM 128
#define N_EDGES 3200000

// Scratch for h = X @ W  (51.2 MB, static device array — no allocs allowed)
__device__ float g_h[(size_t)N_NODES * OUT_DIM];

__device__ __forceinline__ uint32_t smem_u32(const void* p) {
    uint32_t a;
    asm("{ .reg .u64 t; cvta.to.shared.u64 t, %1; cvt.u32.u64 %0, t; }"
        : "=r"(a) : "l"(p));
    return a;
}

// ===========================================================================
// Kernel 1: out[n, c] = b[c]
// ===========================================================================
__global__ void init_bias_kernel(float* __restrict__ out, const float* __restrict__ b) {
    const int total4 = (N_NODES * OUT_DIM) / 4;
    int idx = blockIdx.x * blockDim.x + threadIdx.x;
    const float4* b4 = (const float4*)b;
    for (int i = idx; i < total4; i += gridDim.x * blockDim.x) {
        ((float4*)out)[i] = b4[i & 31];
    }
}

// ===========================================================================
// Kernel 2: mma.sync bf16 3-term GEMM (baseline PTX — no 'a' features).
//   h[N,128] = X[N,256] @ W[256,128]
//   fp32 -> bf16 hi + lo;  D = Ah*Bh + Ah*Bl + Al*Bh  (fp32 accumulate)
// CTA tile 128x128, 8 warps (4x2) of 32x64, K chunked by 32.
// ===========================================================================
#define CH_K   32
#define A_PAD  40            // 32 + 8 bf16 row stride
#define B_PAD  136           // 128 + 8 bf16 row stride
#define A_ELE  (128 * A_PAD) // 5120 bf16 per precision
#define B_ELE  (CH_K * B_PAD)// 4352

__device__ __forceinline__ void ldmx4(uint32_t* r, uint32_t addr) {
    asm volatile("ldmatrix.sync.aligned.m8n8.x4.shared.b16 {%0,%1,%2,%3}, [%4];"
                 : "=r"(r[0]), "=r"(r[1]), "=r"(r[2]), "=r"(r[3]) : "r"(addr));
}
__device__ __forceinline__ void ldmx4t(uint32_t* r, uint32_t addr) {
    asm volatile("ldmatrix.sync.aligned.m8n8.x4.trans.shared.b16 {%0,%1,%2,%3}, [%4];"
                 : "=r"(r[0]), "=r"(r[1]), "=r"(r[2]), "=r"(r[3]) : "r"(addr));
}
__device__ __forceinline__ void mma_bf16(float* c, const uint32_t* a,
                                         uint32_t b0, uint32_t b1) {
    asm volatile(
        "mma.sync.aligned.m16n8k16.row.col.f32.bf16.bf16.f32 "
        "{%0,%1,%2,%3}, {%4,%5,%6,%7}, {%8,%9}, {%0,%1,%2,%3};"
        : "+f"(c[0]), "+f"(c[1]), "+f"(c[2]), "+f"(c[3])
        : "r"(a[0]), "r"(a[1]), "r"(a[2]), "r"(a[3]), "r"(b0), "r"(b1));
}

__device__ __forceinline__ uint32_t pack_bf2(float a, float b) {
    __nv_bfloat16 ha = __float2bfloat16_rn(a);
    __nv_bfloat16 hb = __float2bfloat16_rn(b);
    return ((uint32_t)__bfloat16_as_ushort(hb) << 16) | (uint32_t)__bfloat16_as_ushort(ha);
}

__global__ void __launch_bounds__(256) gemm_mma_kernel(const float* __restrict__ X,
                                                       const float* __restrict__ W) {
    __shared__ __align__(16) __nv_bfloat16 sA[2][A_ELE];  // [hi|lo][128 x 32 padded]
    __shared__ __align__(16) __nv_bfloat16 sB[2][B_ELE];  // [hi|lo][32 x 128 padded]

    const int tid  = threadIdx.x;
    const int wid  = tid >> 5;
    const int lane = tid & 31;
    const int wr   = wid >> 1;   // 0..3  (rows wr*32 .. +31)
    const int wc   = wid & 1;    // 0..1  (cols wc*64 .. +63)
    const int m0   = blockIdx.x * 128;

    const uint32_t sbA = smem_u32(&sA[0][0]);
    const uint32_t sbB = smem_u32(&sB[0][0]);

    float acc[2][8][4];
#pragma unroll
    for (int i = 0; i < 2; i++)
#pragma unroll
        for (int j = 0; j < 8; j++)
#pragma unroll
            for (int q = 0; q < 4; q++) acc[i][j][q] = 0.0f;

    for (int ck = 0; ck < IN_DIM / CH_K; ck++) {
        const int k0 = ck * CH_K;
        __syncthreads();   // previous chunk's mma reads done

        // ---- load A chunk: X[m0:m0+128, k0:k0+32] -> hi/lo bf16 ----
#pragma unroll
        for (int it = 0; it < 4; it++) {
            int i = tid + it * 256;
            int r  = i >> 3;            // 8 float4 per 32-col row
            int c4 = (i & 7) << 2;
            float4 v = make_float4(0.f, 0.f, 0.f, 0.f);
            int m = m0 + r;
            if (m < N_NODES)
                v = *(const float4*)&X[(size_t)m * IN_DIM + k0 + c4];
            float hx = __bfloat162float(__float2bfloat16_rn(v.x));
            float hy = __bfloat162float(__float2bfloat16_rn(v.y));
            float hz = __bfloat162float(__float2bfloat16_rn(v.z));
            float hw = __bfloat162float(__float2bfloat16_rn(v.w));
            *(uint2*)&sA[0][r * A_PAD + c4] =
                make_uint2(pack_bf2(v.x, v.y), pack_bf2(v.z, v.w));
            *(uint2*)&sA[1][r * A_PAD + c4] =
                make_uint2(pack_bf2(v.x - hx, v.y - hy), pack_bf2(v.z - hz, v.w - hw));
        }
        // ---- load B chunk: W[k0:k0+32, 0:128] -> hi/lo bf16 (k-major rows) ----
#pragma unroll
        for (int it = 0; it < 4; it++) {
            int i = tid + it * 256;
            int r  = i >> 5;            // 32 float4 per 128-col row
            int c4 = (i & 31) << 2;
            float4 v = *(const float4*)&W[(size_t)(k0 + r) * OUT_DIM + c4];
            float hx = __bfloat162float(__float2bfloat16_rn(v.x));
            float hy = __bfloat162float(__float2bfloat16_rn(v.y));
            float hz = __bfloat162float(__float2bfloat16_rn(v.z));
            float hw = __bfloat162float(__float2bfloat16_rn(v.w));
            *(uint2*)&sB[0][r * B_PAD + c4] =
                make_uint2(pack_bf2(v.x, v.y), pack_bf2(v.z, v.w));
            *(uint2*)&sB[1][r * B_PAD + c4] =
                make_uint2(pack_bf2(v.x - hx, v.y - hy), pack_bf2(v.z - hz, v.w - hw));
        }
        __syncthreads();

        // ---- compute: 2 k16 steps per chunk ----
#pragma unroll
        for (int ks = 0; ks < CH_K / 16; ks++) {
            uint32_t ahi[2][4], alo[2][4];
#pragma unroll
            for (int i = 0; i < 2; i++) {
                int aRow = wr * 32 + i * 16 + (lane & 15);
                uint32_t off = (uint32_t)(aRow * A_PAD + ks * 16 + (lane >> 4) * 8) * 2;
                ldmx4(ahi[i], sbA + off);
                ldmx4(alo[i], sbA + A_ELE * 2 + off);
            }
            uint32_t bhi[4][4], blo[4][4];
#pragma unroll
            for (int j2 = 0; j2 < 4; j2++) {
                int bK = ks * 16 + (lane & 7) + ((lane >> 3) & 1) * 8;
                int bN = wc * 64 + j2 * 16 + (lane >> 4) * 8;
                uint32_t off = (uint32_t)(bK * B_PAD + bN) * 2;
                ldmx4t(bhi[j2], sbB + off);
                ldmx4t(blo[j2], sbB + B_ELE * 2 + off);
            }
#pragma unroll
            for (int i = 0; i < 2; i++)
#pragma unroll
                for (int j = 0; j < 8; j++) {
                    int j2 = j >> 1, pr = (j & 1) * 2;
                    mma_bf16(acc[i][j], ahi[i], bhi[j2][pr], bhi[j2][pr + 1]);
                    mma_bf16(acc[i][j], ahi[i], blo[j2][pr], blo[j2][pr + 1]);
                    mma_bf16(acc[i][j], alo[i], bhi[j2][pr], bhi[j2][pr + 1]);
                }
        }
    }

    // ---- epilogue: write g_h ----
#pragma unroll
    for (int i = 0; i < 2; i++) {
        int mA = m0 + wr * 32 + i * 16 + (lane >> 2);
        int mB = mA + 8;
#pragma unroll
        for (int j = 0; j < 8; j++) {
            int col = wc * 64 + j * 8 + (lane & 3) * 2;
            if (mA < N_NODES)
                *(float2*)&g_h[(size_t)mA * OUT_DIM + col] =
                    make_float2(acc[i][j][0], acc[i][j][1]);
            if (mB < N_NODES)
                *(float2*)&g_h[(size_t)mB * OUT_DIM + col] =
                    make_float2(acc[i][j][2], acc[i][j][3]);
        }
    }
}

// ===========================================================================
// Kernel 3: scatter. One warp per 32 edges; warp covers all 128 feats/edge.
// ===========================================================================
__global__ __launch_bounds__(256) void scatter_kernel(const int* __restrict__ src,
                                                      const int* __restrict__ dst,
                                                      const float* __restrict__ val,
                                                      float* __restrict__ out) {
    const int warp = (blockIdx.x * blockDim.x + threadIdx.x) >> 5;
    const int lane = threadIdx.x & 31;
    const int base = warp * 32;
    if (base >= N_EDGES) return;

    int   s = src[base + lane];
    int   d = dst[base + lane];
    float v = val[base + lane];

#pragma unroll 4
    for (int j = 0; j < 32; j++) {
        int   sj = __shfl_sync(0xffffffffu, s, j);
        int   dj = __shfl_sync(0xffffffffu, d, j);
        float vj = __shfl_sync(0xffffffffu, v, j);

        float4 h4 = *(const float4*)&g_h[(size_t)sj * OUT_DIM + lane * 4];
        float4 m4 = make_float4(h4.x * vj, h4.y * vj, h4.z * vj, h4.w * vj);

        float* p = &out[(size_t)dj * OUT_DIM + lane * 4];
        asm volatile("red.global.add.v4.f32 [%0], {%1, %2, %3, %4};"
                     :: "l"(p), "f"(m4.x), "f"(m4.y), "f"(m4.z), "f"(m4.w)
                     : "memory");
    }
}

// ===========================================================================
// Launch
// ===========================================================================
extern "C" void kernel_launch(void* const* d_in, const int* in_sizes, int n_in,
                              void* d_out, int out_size) {
    const float* feature_map = (const float*)d_in[0];
    const int*   edge_src    = (const int*)d_in[1];
    const int*   edge_dst    = (const int*)d_in[2];
    const float* edge_vals   = (const float*)d_in[3];
    const float* weights     = (const float*)d_in[4];
    const float* bias        = (const float*)d_in[5];
    float*       out         = (float*)d_out;

    // 1. out = bias (clears poison)
    init_bias_kernel<<<1024, 256>>>(out, bias);

    // 2. h = X @ W on HMMA tensor cores (bf16 3-term, fp32-accurate)
    gemm_mma_kernel<<<(N_NODES + 127) / 128, 256>>>(feature_map, weights);

    // 3. scatter-add messages
    scatter_kernel<<<N_EDGES / 256, 256>>>(edge_src, edge_dst, edge_vals, out);

    (void)in_sizes; (void)n_in; (void)out_size;
}

// round 4
// speedup vs baseline: 1.6103x; 1.4319x over previous
#include <cuda_runtime.h>
#include <cuda_bf16.h>
#include <cstdint>

// Problem constants (fixed by the dataset)
#define N_NODES 100000
#define IN_DIM  256
#define OUT_DIM 128
#define N_EDGES 3200000

#define NB_SCAN_BLOCKS 98
#define NB_BINS (NB_SCAN_BLOCKS * 1024)   // 100352 >= N_NODES

// Static device scratch (no allocations allowed)
__device__ float g_h[(size_t)N_NODES * OUT_DIM];          // 51.2 MB
__device__ int2  g_edge[N_EDGES];                         // 25.6 MB (src, val-bits) sorted by dst
__device__ int   g_cnt[NB_BINS];
__device__ int   g_rowptr[NB_BINS];
__device__ int   g_cursor[NB_BINS];
__device__ int   g_bsum[NB_SCAN_BLOCKS];

__device__ __forceinline__ uint32_t smem_u32(const void* p) {
    uint32_t a;
    asm("{ .reg .u64 t; cvta.to.shared.u64 t, %1; cvt.u32.u64 %0, t; }"
        : "=r"(a) : "l"(p));
    return a;
}

// ===========================================================================
// Sort chain: zero -> histogram -> scan(3) -> placement
// ===========================================================================
__global__ void zero_cnt_kernel() {
    int i = blockIdx.x * blockDim.x + threadIdx.x;
    if (i < NB_BINS) g_cnt[i] = 0;
}

__global__ void hist_kernel(const int* __restrict__ dst) {
    int i = blockIdx.x * blockDim.x + threadIdx.x;
    if (i < N_EDGES) atomicAdd(&g_cnt[dst[i]], 1);   // no return use -> RED
}

__global__ __launch_bounds__(1024) void scan1_kernel() {
    __shared__ int s[1024];
    int t = threadIdx.x;
    int i = blockIdx.x * 1024 + t;
    int v = g_cnt[i];
    s[t] = v;
    __syncthreads();
    // Hillis-Steele inclusive scan
#pragma unroll
    for (int off = 1; off < 1024; off <<= 1) {
        int add = (t >= off) ? s[t - off] : 0;
        __syncthreads();
        s[t] += add;
        __syncthreads();
    }
    g_rowptr[i] = s[t] - v;               // exclusive prefix within block
    if (t == 1023) g_bsum[blockIdx.x] = s[t];
}

__global__ void scan2_kernel() {
    if (threadIdx.x == 0) {
        int acc = 0;
        for (int b = 0; b < NB_SCAN_BLOCKS; b++) {
            int v = g_bsum[b];
            g_bsum[b] = acc;
            acc += v;
        }
    }
}

__global__ __launch_bounds__(1024) void scan3_kernel() {
    int i = blockIdx.x * 1024 + threadIdx.x;
    int rp = g_rowptr[i] + g_bsum[blockIdx.x];
    g_rowptr[i] = rp;
    g_cursor[i] = rp;
}

__global__ void place_kernel(const int* __restrict__ src,
                             const int* __restrict__ dst,
                             const float* __restrict__ val) {
    int i = blockIdx.x * blockDim.x + threadIdx.x;
    if (i < N_EDGES) {
        int d = dst[i];
        int pos = atomicAdd(&g_cursor[d], 1);
        g_edge[pos] = make_int2(src[i], __float_as_int(val[i]));
    }
}

// ===========================================================================
// GEMM: mma.sync bf16 3-term (unchanged from R3 — passed at rel_err 4.7e-6)
// ===========================================================================
#define CH_K   32
#define A_PAD  40
#define B_PAD  136
#define A_ELE  (128 * A_PAD)
#define B_ELE  (CH_K * B_PAD)

__device__ __forceinline__ void ldmx4(uint32_t* r, uint32_t addr) {
    asm volatile("ldmatrix.sync.aligned.m8n8.x4.shared.b16 {%0,%1,%2,%3}, [%4];"
                 : "=r"(r[0]), "=r"(r[1]), "=r"(r[2]), "=r"(r[3]) : "r"(addr));
}
__device__ __forceinline__ void ldmx4t(uint32_t* r, uint32_t addr) {
    asm volatile("ldmatrix.sync.aligned.m8n8.x4.trans.shared.b16 {%0,%1,%2,%3}, [%4];"
                 : "=r"(r[0]), "=r"(r[1]), "=r"(r[2]), "=r"(r[3]) : "r"(addr));
}
__device__ __forceinline__ void mma_bf16(float* c, const uint32_t* a,
                                         uint32_t b0, uint32_t b1) {
    asm volatile(
        "mma.sync.aligned.m16n8k16.row.col.f32.bf16.bf16.f32 "
        "{%0,%1,%2,%3}, {%4,%5,%6,%7}, {%8,%9}, {%0,%1,%2,%3};"
        : "+f"(c[0]), "+f"(c[1]), "+f"(c[2]), "+f"(c[3])
        : "r"(a[0]), "r"(a[1]), "r"(a[2]), "r"(a[3]), "r"(b0), "r"(b1));
}
__device__ __forceinline__ uint32_t pack_bf2(float a, float b) {
    __nv_bfloat16 ha = __float2bfloat16_rn(a);
    __nv_bfloat16 hb = __float2bfloat16_rn(b);
    return ((uint32_t)__bfloat16_as_ushort(hb) << 16) | (uint32_t)__bfloat16_as_ushort(ha);
}

__global__ void __launch_bounds__(256) gemm_mma_kernel(const float* __restrict__ X,
                                                       const float* __restrict__ W) {
    __shared__ __align__(16) __nv_bfloat16 sA[2][A_ELE];
    __shared__ __align__(16) __nv_bfloat16 sB[2][B_ELE];

    const int tid  = threadIdx.x;
    const int wid  = tid >> 5;
    const int lane = tid & 31;
    const int wr   = wid >> 1;
    const int wc   = wid & 1;
    const int m0   = blockIdx.x * 128;

    const uint32_t sbA = smem_u32(&sA[0][0]);
    const uint32_t sbB = smem_u32(&sB[0][0]);

    float acc[2][8][4];
#pragma unroll
    for (int i = 0; i < 2; i++)
#pragma unroll
        for (int j = 0; j < 8; j++)
#pragma unroll
            for (int q = 0; q < 4; q++) acc[i][j][q] = 0.0f;

    for (int ck = 0; ck < IN_DIM / CH_K; ck++) {
        const int k0 = ck * CH_K;
        __syncthreads();
#pragma unroll
        for (int it = 0; it < 4; it++) {
            int i = tid + it * 256;
            int r  = i >> 3;
            int c4 = (i & 7) << 2;
            float4 v = make_float4(0.f, 0.f, 0.f, 0.f);
            int m = m0 + r;
            if (m < N_NODES)
                v = *(const float4*)&X[(size_t)m * IN_DIM + k0 + c4];
            float hx = __bfloat162float(__float2bfloat16_rn(v.x));
            float hy = __bfloat162float(__float2bfloat16_rn(v.y));
            float hz = __bfloat162float(__float2bfloat16_rn(v.z));
            float hw = __bfloat162float(__float2bfloat16_rn(v.w));
            *(uint2*)&sA[0][r * A_PAD + c4] =
                make_uint2(pack_bf2(v.x, v.y), pack_bf2(v.z, v.w));
            *(uint2*)&sA[1][r * A_PAD + c4] =
                make_uint2(pack_bf2(v.x - hx, v.y - hy), pack_bf2(v.z - hz, v.w - hw));
        }
#pragma unroll
        for (int it = 0; it < 4; it++) {
            int i = tid + it * 256;
            int r  = i >> 5;
            int c4 = (i & 31) << 2;
            float4 v = *(const float4*)&W[(size_t)(k0 + r) * OUT_DIM + c4];
            float hx = __bfloat162float(__float2bfloat16_rn(v.x));
            float hy = __bfloat162float(__float2bfloat16_rn(v.y));
            float hz = __bfloat162float(__float2bfloat16_rn(v.z));
            float hw = __bfloat162float(__float2bfloat16_rn(v.w));
            *(uint2*)&sB[0][r * B_PAD + c4] =
                make_uint2(pack_bf2(v.x, v.y), pack_bf2(v.z, v.w));
            *(uint2*)&sB[1][r * B_PAD + c4] =
                make_uint2(pack_bf2(v.x - hx, v.y - hy), pack_bf2(v.z - hz, v.w - hw));
        }
        __syncthreads();

#pragma unroll
        for (int ks = 0; ks < CH_K / 16; ks++) {
            uint32_t ahi[2][4], alo[2][4];
#pragma unroll
            for (int i = 0; i < 2; i++) {
                int aRow = wr * 32 + i * 16 + (lane & 15);
                uint32_t off = (uint32_t)(aRow * A_PAD + ks * 16 + (lane >> 4) * 8) * 2;
                ldmx4(ahi[i], sbA + off);
                ldmx4(alo[i], sbA + A_ELE * 2 + off);
            }
            uint32_t bhi[4][4], blo[4][4];
#pragma unroll
            for (int j2 = 0; j2 < 4; j2++) {
                int bK = ks * 16 + (lane & 7) + ((lane >> 3) & 1) * 8;
                int bN = wc * 64 + j2 * 16 + (lane >> 4) * 8;
                uint32_t off = (uint32_t)(bK * B_PAD + bN) * 2;
                ldmx4t(bhi[j2], sbB + off);
                ldmx4t(blo[j2], sbB + B_ELE * 2 + off);
            }
#pragma unroll
            for (int i = 0; i < 2; i++)
#pragma unroll
                for (int j = 0; j < 8; j++) {
                    int j2 = j >> 1, pr = (j & 1) * 2;
                    mma_bf16(acc[i][j], ahi[i], bhi[j2][pr], bhi[j2][pr + 1]);
                    mma_bf16(acc[i][j], ahi[i], blo[j2][pr], blo[j2][pr + 1]);
                    mma_bf16(acc[i][j], alo[i], bhi[j2][pr], bhi[j2][pr + 1]);
                }
        }
    }

#pragma unroll
    for (int i = 0; i < 2; i++) {
        int mA = m0 + wr * 32 + i * 16 + (lane >> 2);
        int mB = mA + 8;
#pragma unroll
        for (int j = 0; j < 8; j++) {
            int col = wc * 64 + j * 8 + (lane & 3) * 2;
            if (mA < N_NODES)
                *(float2*)&g_h[(size_t)mA * OUT_DIM + col] =
                    make_float2(acc[i][j][0], acc[i][j][1]);
            if (mB < N_NODES)
                *(float2*)&g_h[(size_t)mB * OUT_DIM + col] =
                    make_float2(acc[i][j][2], acc[i][j][3]);
        }
    }
}

// ===========================================================================
// Gather: one warp per dst node. Accumulate messages in registers, write once
// (bias fused). After place_kernel, g_cursor[n] == row_end(n).
// ===========================================================================
__global__ __launch_bounds__(256) void gather_kernel(const float* __restrict__ b,
                                                     float* __restrict__ out) {
    const int warp = (blockIdx.x * blockDim.x + threadIdx.x) >> 5;
    const int lane = threadIdx.x & 31;
    if (warp >= N_NODES) return;

    const int start = g_rowptr[warp];
    const int end   = g_cursor[warp];

    float4 acc = ((const float4*)b)[lane];   // bias init

#pragma unroll 4
    for (int e = start; e < end; e++) {
        int2 ed = g_edge[e];                 // broadcast load (same addr all lanes)
        float vj = __int_as_float(ed.y);
        float4 h4 = *(const float4*)&g_h[(size_t)ed.x * OUT_DIM + lane * 4];
        acc.x = fmaf(vj, h4.x, acc.x);
        acc.y = fmaf(vj, h4.y, acc.y);
        acc.z = fmaf(vj, h4.z, acc.z);
        acc.w = fmaf(vj, h4.w, acc.w);
    }
    *(float4*)&out[(size_t)warp * OUT_DIM + lane * 4] = acc;
}

// ===========================================================================
// Launch
// ===========================================================================
extern "C" void kernel_launch(void* const* d_in, const int* in_sizes, int n_in,
                              void* d_out, int out_size) {
    const float* feature_map = (const float*)d_in[0];
    const int*   edge_src    = (const int*)d_in[1];
    const int*   edge_dst    = (const int*)d_in[2];
    const float* edge_vals   = (const float*)d_in[3];
    const float* weights     = (const float*)d_in[4];
    const float* bias        = (const float*)d_in[5];
    float*       out         = (float*)d_out;

    // Sort chain (independent of GEMM)
    zero_cnt_kernel<<<(NB_BINS + 255) / 256, 256>>>();
    hist_kernel<<<(N_EDGES + 255) / 256, 256>>>(edge_dst);
    scan1_kernel<<<NB_SCAN_BLOCKS, 1024>>>();
    scan2_kernel<<<1, 32>>>();
    scan3_kernel<<<NB_SCAN_BLOCKS, 1024>>>();
    place_kernel<<<(N_EDGES + 255) / 256, 256>>>(edge_src, edge_dst, edge_vals);

    // h = X @ W on tensor cores
    gemm_mma_kernel<<<(N_NODES + 127) / 128, 256>>>(feature_map, weights);

    // Gather + bias (writes every output row exactly once)
    gather_kernel<<<(N_NODES * 32 + 255) / 256, 256>>>(bias, out);

    (void)in_sizes; (void)n_in; (void)out_size;
}

// round 5
// speedup vs baseline: 1.7285x; 1.0734x over previous
#include <cuda_runtime.h>
#include <cuda_bf16.h>
#include <cuda_fp16.h>
#include <cstdint>

// Problem constants (fixed by the dataset)
#define N_NODES 100000
#define IN_DIM  256
#define OUT_DIM 128
#define N_EDGES 3200000

#define NB_SCAN_BLOCKS 98
#define NB_BINS (NB_SCAN_BLOCKS * 1024)   // 100352 >= N_NODES

// Static device scratch (no allocations allowed)
__device__ __half g_h[(size_t)N_NODES * OUT_DIM];          // 25.6 MB (fp16 h)
__device__ int2   g_edge[N_EDGES];                         // 25.6 MB, sorted by dst
__device__ int    g_cnt[NB_BINS];
__device__ int    g_rowptr[NB_BINS];
__device__ int    g_cursor[NB_BINS];
__device__ int    g_bsum[NB_SCAN_BLOCKS];

__device__ __forceinline__ uint32_t smem_u32(const void* p) {
    uint32_t a;
    asm("{ .reg .u64 t; cvta.to.shared.u64 t, %1; cvt.u32.u64 %0, t; }"
        : "=r"(a) : "l"(p));
    return a;
}

// ===========================================================================
// Sort chain: zero -> histogram -> scan(3) -> placement
// ===========================================================================
__global__ void zero_cnt_kernel() {
    int i = blockIdx.x * blockDim.x + threadIdx.x;
    if (i < NB_BINS) g_cnt[i] = 0;
}

__global__ void hist_kernel(const int* __restrict__ dst) {
    int i = blockIdx.x * blockDim.x + threadIdx.x;
    if (i < N_EDGES) atomicAdd(&g_cnt[dst[i]], 1);
}

__global__ __launch_bounds__(1024) void scan1_kernel() {
    __shared__ int s[1024];
    int t = threadIdx.x;
    int i = blockIdx.x * 1024 + t;
    int v = g_cnt[i];
    s[t] = v;
    __syncthreads();
#pragma unroll
    for (int off = 1; off < 1024; off <<= 1) {
        int add = (t >= off) ? s[t - off] : 0;
        __syncthreads();
        s[t] += add;
        __syncthreads();
    }
    g_rowptr[i] = s[t] - v;
    if (t == 1023) g_bsum[blockIdx.x] = s[t];
}

// Parallel block-sums scan: one block of 128 threads (NB_SCAN_BLOCKS=98 <= 128)
__global__ __launch_bounds__(128) void scan2_kernel() {
    __shared__ int s[128];
    int t = threadIdx.x;
    int v = (t < NB_SCAN_BLOCKS) ? g_bsum[t] : 0;
    s[t] = v;
    __syncthreads();
#pragma unroll
    for (int off = 1; off < 128; off <<= 1) {
        int add = (t >= off) ? s[t - off] : 0;
        __syncthreads();
        s[t] += add;
        __syncthreads();
    }
    if (t < NB_SCAN_BLOCKS) g_bsum[t] = s[t] - v;   // exclusive
}

__global__ __launch_bounds__(1024) void scan3_kernel() {
    int i = blockIdx.x * 1024 + threadIdx.x;
    int rp = g_rowptr[i] + g_bsum[blockIdx.x];
    g_rowptr[i] = rp;
    g_cursor[i] = rp;
}

__global__ void place_kernel(const int* __restrict__ src,
                             const int* __restrict__ dst,
                             const float* __restrict__ val) {
    int i = blockIdx.x * blockDim.x + threadIdx.x;
    if (i < N_EDGES) {
        int d = dst[i];
        int pos = atomicAdd(&g_cursor[d], 1);
        g_edge[pos] = make_int2(src[i], __float_as_int(val[i]));
    }
}

// ===========================================================================
// GEMM: mma.sync bf16 3-term.  h[N,128] = X[N,256] @ W[256,128] -> fp16 store
// ===========================================================================
#define CH_K   32
#define A_PAD  40
#define B_PAD  136
#define A_ELE  (128 * A_PAD)
#define B_ELE  (CH_K * B_PAD)

__device__ __forceinline__ void ldmx4(uint32_t* r, uint32_t addr) {
    asm volatile("ldmatrix.sync.aligned.m8n8.x4.shared.b16 {%0,%1,%2,%3}, [%4];"
                 : "=r"(r[0]), "=r"(r[1]), "=r"(r[2]), "=r"(r[3]) : "r"(addr));
}
__device__ __forceinline__ void ldmx4t(uint32_t* r, uint32_t addr) {
    asm volatile("ldmatrix.sync.aligned.m8n8.x4.trans.shared.b16 {%0,%1,%2,%3}, [%4];"
                 : "=r"(r[0]), "=r"(r[1]), "=r"(r[2]), "=r"(r[3]) : "r"(addr));
}
__device__ __forceinline__ void mma_bf16(float* c, const uint32_t* a,
                                         uint32_t b0, uint32_t b1) {
    asm volatile(
        "mma.sync.aligned.m16n8k16.row.col.f32.bf16.bf16.f32 "
        "{%0,%1,%2,%3}, {%4,%5,%6,%7}, {%8,%9}, {%0,%1,%2,%3};"
        : "+f"(c[0]), "+f"(c[1]), "+f"(c[2]), "+f"(c[3])
        : "r"(a[0]), "r"(a[1]), "r"(a[2]), "r"(a[3]), "r"(b0), "r"(b1));
}
__device__ __forceinline__ uint32_t pack_bf2(float a, float b) {
    __nv_bfloat16 ha = __float2bfloat16_rn(a);
    __nv_bfloat16 hb = __float2bfloat16_rn(b);
    return ((uint32_t)__bfloat16_as_ushort(hb) << 16) | (uint32_t)__bfloat16_as_ushort(ha);
}

__global__ void __launch_bounds__(256) gemm_mma_kernel(const float* __restrict__ X,
                                                       const float* __restrict__ W) {
    __shared__ __align__(16) __nv_bfloat16 sA[2][A_ELE];
    __shared__ __align__(16) __nv_bfloat16 sB[2][B_ELE];

    const int tid  = threadIdx.x;
    const int wid  = tid >> 5;
    const int lane = tid & 31;
    const int wr   = wid >> 1;
    const int wc   = wid & 1;
    const int m0   = blockIdx.x * 128;

    const uint32_t sbA = smem_u32(&sA[0][0]);
    const uint32_t sbB = smem_u32(&sB[0][0]);

    float acc[2][8][4];
#pragma unroll
    for (int i = 0; i < 2; i++)
#pragma unroll
        for (int j = 0; j < 8; j++)
#pragma unroll
            for (int q = 0; q < 4; q++) acc[i][j][q] = 0.0f;

    for (int ck = 0; ck < IN_DIM / CH_K; ck++) {
        const int k0 = ck * CH_K;
        __syncthreads();
#pragma unroll
        for (int it = 0; it < 4; it++) {
            int i = tid + it * 256;
            int r  = i >> 3;
            int c4 = (i & 7) << 2;
            float4 v = make_float4(0.f, 0.f, 0.f, 0.f);
            int m = m0 + r;
            if (m < N_NODES)
                v = *(const float4*)&X[(size_t)m * IN_DIM + k0 + c4];
            float hx = __bfloat162float(__float2bfloat16_rn(v.x));
            float hy = __bfloat162float(__float2bfloat16_rn(v.y));
            float hz = __bfloat162float(__float2bfloat16_rn(v.z));
            float hw = __bfloat162float(__float2bfloat16_rn(v.w));
            *(uint2*)&sA[0][r * A_PAD + c4] =
                make_uint2(pack_bf2(v.x, v.y), pack_bf2(v.z, v.w));
            *(uint2*)&sA[1][r * A_PAD + c4] =
                make_uint2(pack_bf2(v.x - hx, v.y - hy), pack_bf2(v.z - hz, v.w - hw));
        }
#pragma unroll
        for (int it = 0; it < 4; it++) {
            int i = tid + it * 256;
            int r  = i >> 5;
            int c4 = (i & 31) << 2;
            float4 v = *(const float4*)&W[(size_t)(k0 + r) * OUT_DIM + c4];
            float hx = __bfloat162float(__float2bfloat16_rn(v.x));
            float hy = __bfloat162float(__float2bfloat16_rn(v.y));
            float hz = __bfloat162float(__float2bfloat16_rn(v.z));
            float hw = __bfloat162float(__float2bfloat16_rn(v.w));
            *(uint2*)&sB[0][r * B_PAD + c4] =
                make_uint2(pack_bf2(v.x, v.y), pack_bf2(v.z, v.w));
            *(uint2*)&sB[1][r * B_PAD + c4] =
                make_uint2(pack_bf2(v.x - hx, v.y - hy), pack_bf2(v.z - hz, v.w - hw));
        }
        __syncthreads();

#pragma unroll
        for (int ks = 0; ks < CH_K / 16; ks++) {
            uint32_t ahi[2][4], alo[2][4];
#pragma unroll
            for (int i = 0; i < 2; i++) {
                int aRow = wr * 32 + i * 16 + (lane & 15);
                uint32_t off = (uint32_t)(aRow * A_PAD + ks * 16 + (lane >> 4) * 8) * 2;
                ldmx4(ahi[i], sbA + off);
                ldmx4(alo[i], sbA + A_ELE * 2 + off);
            }
            uint32_t bhi[4][4], blo[4][4];
#pragma unroll
            for (int j2 = 0; j2 < 4; j2++) {
                int bK = ks * 16 + (lane & 7) + ((lane >> 3) & 1) * 8;
                int bN = wc * 64 + j2 * 16 + (lane >> 4) * 8;
                uint32_t off = (uint32_t)(bK * B_PAD + bN) * 2;
                ldmx4t(bhi[j2], sbB + off);
                ldmx4t(blo[j2], sbB + B_ELE * 2 + off);
            }
#pragma unroll
            for (int i = 0; i < 2; i++)
#pragma unroll
                for (int j = 0; j < 8; j++) {
                    int j2 = j >> 1, pr = (j & 1) * 2;
                    mma_bf16(acc[i][j], ahi[i], bhi[j2][pr], bhi[j2][pr + 1]);
                    mma_bf16(acc[i][j], ahi[i], blo[j2][pr], blo[j2][pr + 1]);
                    mma_bf16(acc[i][j], alo[i], bhi[j2][pr], bhi[j2][pr + 1]);
                }
        }
    }

    // epilogue: fp32 acc -> fp16 store (2 cols per half2)
#pragma unroll
    for (int i = 0; i < 2; i++) {
        int mA = m0 + wr * 32 + i * 16 + (lane >> 2);
        int mB = mA + 8;
#pragma unroll
        for (int j = 0; j < 8; j++) {
            int col = wc * 64 + j * 8 + (lane & 3) * 2;
            if (mA < N_NODES)
                *(__half2*)&g_h[(size_t)mA * OUT_DIM + col] =
                    __floats2half2_rn(acc[i][j][0], acc[i][j][1]);
            if (mB < N_NODES)
                *(__half2*)&g_h[(size_t)mB * OUT_DIM + col] =
                    __floats2half2_rn(acc[i][j][2], acc[i][j][3]);
        }
    }
}

// ===========================================================================
// Gather: one warp per dst node; lane covers 4 feature cols (half2 x2).
// fp32 accumulate, bias fused, single write per output row.
// ===========================================================================
__global__ __launch_bounds__(256) void gather_kernel(const float* __restrict__ b,
                                                     float* __restrict__ out) {
    const int warp = (blockIdx.x * blockDim.x + threadIdx.x) >> 5;
    const int lane = threadIdx.x & 31;
    if (warp >= N_NODES) return;

    const int start = g_rowptr[warp];
    const int end   = g_cursor[warp];

    float4 acc = ((const float4*)b)[lane];   // bias init

#pragma unroll 4
    for (int e = start; e < end; e++) {
        int2 ed = g_edge[e];                 // broadcast load
        float vj = __int_as_float(ed.y);
        uint2 raw = *(const uint2*)&g_h[(size_t)ed.x * OUT_DIM + lane * 4];
        float2 h01 = __half22float2(*(__half2*)&raw.x);
        float2 h23 = __half22float2(*(__half2*)&raw.y);
        acc.x = fmaf(vj, h01.x, acc.x);
        acc.y = fmaf(vj, h01.y, acc.y);
        acc.z = fmaf(vj, h23.x, acc.z);
        acc.w = fmaf(vj, h23.y, acc.w);
    }
    *(float4*)&out[(size_t)warp * OUT_DIM + lane * 4] = acc;
}

// ===========================================================================
// Launch
// ===========================================================================
extern "C" void kernel_launch(void* const* d_in, const int* in_sizes, int n_in,
                              void* d_out, int out_size) {
    const float* feature_map = (const float*)d_in[0];
    const int*   edge_src    = (const int*)d_in[1];
    const int*   edge_dst    = (const int*)d_in[2];
    const float* edge_vals   = (const float*)d_in[3];
    const float* weights     = (const float*)d_in[4];
    const float* bias        = (const float*)d_in[5];
    float*       out         = (float*)d_out;

    // Sort chain
    zero_cnt_kernel<<<(NB_BINS + 255) / 256, 256>>>();
    hist_kernel<<<(N_EDGES + 255) / 256, 256>>>(edge_dst);
    scan1_kernel<<<NB_SCAN_BLOCKS, 1024>>>();
    scan2_kernel<<<1, 128>>>();
    scan3_kernel<<<NB_SCAN_BLOCKS, 1024>>>();
    place_kernel<<<(N_EDGES + 255) / 256, 256>>>(edge_src, edge_dst, edge_vals);

    // h = X @ W on tensor cores (fp16 output)
    gemm_mma_kernel<<<(N_NODES + 127) / 128, 256>>>(feature_map, weights);

    // Gather + bias
    gather_kernel<<<(N_NODES * 32 + 255) / 256, 256>>>(bias, out);

    (void)in_sizes; (void)n_in; (void)out_size;
}